// round 2
// baseline (speedup 1.0000x reference)
#include <cuda_runtime.h>

#define N       8192
#define GRID_A  296          // 2 blocks per SM * 148 SMs, one wave
#define BLK_A   512
#define NITER   10
#define PGROUPS 8
#define P_PER_G (GRID_A / PGROUPS)   // 37

__device__ float g_c[N];
__device__ float g_r[N];
__device__ float g_part[(size_t)GRID_A * N];

// ---------------------------------------------------------------------------
// zero the column log-offset vector (must happen every kernel_launch call)
// ---------------------------------------------------------------------------
__global__ void init_c_kernel() {
    int i = blockIdx.x * blockDim.x + threadIdx.x;
    if (i < N) g_c[i] = 0.0f;
}

// ---------------------------------------------------------------------------
// One Sinkhorn iteration's matrix pass:
//   S_i      = sum_j exp(x[i,j] - c[j])          -> r[i] = log(S_i)
//   part[b,j]= sum_{i in block} exp(x[i,j]-c[j]) / S_i
// Each thread owns 16 columns as 4 float4s: float4 index = tid + 512*k.
// ---------------------------------------------------------------------------
__global__ void __launch_bounds__(BLK_A, 2)
row_pass_kernel(const float* __restrict__ X) {
    __shared__ float s_warp[BLK_A / 32];
    __shared__ float s_rcp;

    const int tid  = threadIdx.x;
    const int b    = blockIdx.x;
    const int row0 = (int)(((long long)N * b)       / GRID_A);
    const int row1 = (int)(((long long)N * (b + 1)) / GRID_A);

    // column offsets c[j] for this thread's 16 columns (registers)
    const float4* c4 = (const float4*)g_c;
    float4 cv[4];
#pragma unroll
    for (int k = 0; k < 4; k++) cv[k] = c4[tid + 512 * k];

    float4 acc[4];
#pragma unroll
    for (int k = 0; k < 4; k++) acc[k] = make_float4(0.f, 0.f, 0.f, 0.f);

    for (int row = row0; row < row1; ++row) {
        const float4* xr = (const float4*)(X + (size_t)row * N);
        float4 e[4];
        float  psum = 0.0f;
#pragma unroll
        for (int k = 0; k < 4; k++) {
            float4 x = __ldg(xr + tid + 512 * k);
            e[k].x = __expf(x.x - cv[k].x);
            e[k].y = __expf(x.y - cv[k].y);
            e[k].z = __expf(x.z - cv[k].z);
            e[k].w = __expf(x.w - cv[k].w);
            psum += (e[k].x + e[k].y) + (e[k].z + e[k].w);
        }
        // warp reduce
#pragma unroll
        for (int off = 16; off > 0; off >>= 1)
            psum += __shfl_xor_sync(0xffffffffu, psum, off);
        if ((tid & 31) == 0) s_warp[tid >> 5] = psum;
        __syncthreads();
        if (tid < 32) {
            float v = (tid < BLK_A / 32) ? s_warp[tid] : 0.0f;
#pragma unroll
            for (int off = 8; off > 0; off >>= 1)
                v += __shfl_xor_sync(0xffffffffu, v, off);
            if (tid == 0) {
                s_rcp   = 1.0f / v;          // exp(-r_new[i]) exactly
                g_r[row] = logf(v);          // row log-offset (used by final pass)
            }
        }
        __syncthreads();
        const float rcp = s_rcp;
#pragma unroll
        for (int k = 0; k < 4; k++) {
            acc[k].x = fmaf(e[k].x, rcp, acc[k].x);
            acc[k].y = fmaf(e[k].y, rcp, acc[k].y);
            acc[k].z = fmaf(e[k].z, rcp, acc[k].z);
            acc[k].w = fmaf(e[k].w, rcp, acc[k].w);
        }
    }

    float4* pp = (float4*)(g_part + (size_t)b * N);
#pragma unroll
    for (int k = 0; k < 4; k++) pp[tid + 512 * k] = acc[k];
}

// ---------------------------------------------------------------------------
// Column reduce: c[j] += log( sum_b part[b][j] ).
// 64 blocks x 1024 threads = (128 cols, 8 p-groups) -> high MLP, deterministic.
// ---------------------------------------------------------------------------
__global__ void __launch_bounds__(1024)
col_reduce_kernel() {
    __shared__ float s[PGROUPS][128];
    const int jl = threadIdx.x & 127;
    const int pg = threadIdx.x >> 7;
    const int j  = blockIdx.x * 128 + jl;

    const float* base = g_part + (size_t)(pg * P_PER_G) * N + j;
    float a0 = 0.f, a1 = 0.f, a2 = 0.f, a3 = 0.f;
#pragma unroll
    for (int u = 0; u < 36; u += 4) {
        a0 += base[(size_t)(u + 0) * N];
        a1 += base[(size_t)(u + 1) * N];
        a2 += base[(size_t)(u + 2) * N];
        a3 += base[(size_t)(u + 3) * N];
    }
    a0 += base[(size_t)36 * N];                  // 37th element
    s[pg][jl] = (a0 + a1) + (a2 + a3);
    __syncthreads();

    if (pg == 0) {
        float t = 0.0f;
#pragma unroll
        for (int q = 0; q < PGROUPS; q++) t += s[q][jl];
        g_c[j] += logf(t);
    }
}

// ---------------------------------------------------------------------------
// Final: out[i,j] = exp(x[i,j] - r[i] - c[j])
// ---------------------------------------------------------------------------
__global__ void __launch_bounds__(256)
final_kernel(const float* __restrict__ X, float* __restrict__ out) {
    const size_t idx  = (size_t)blockIdx.x * blockDim.x + threadIdx.x; // float4 index
    const int    row  = (int)(idx >> 11);        // N/4 = 2048 float4 per row
    const int    c4i  = (int)(idx & 2047);

    const float  rv = __ldg(g_r + row);
    const float4 cc = __ldg(((const float4*)g_c) + c4i);
    const float4 x  = __ldg(((const float4*)X) + idx);

    float4 o;
    o.x = __expf(x.x - rv - cc.x);
    o.y = __expf(x.y - rv - cc.y);
    o.z = __expf(x.z - rv - cc.z);
    o.w = __expf(x.w - rv - cc.w);
    ((float4*)out)[idx] = o;
}

// ---------------------------------------------------------------------------
extern "C" void kernel_launch(void* const* d_in, const int* in_sizes, int n_in,
                              void* d_out, int out_size) {
    const float* X   = (const float*)d_in[0];
    float*       out = (float*)d_out;
    (void)in_sizes; (void)n_in; (void)out_size;

    init_c_kernel<<<N / 256, 256>>>();
    for (int it = 0; it < NITER; ++it) {
        row_pass_kernel<<<GRID_A, BLK_A>>>(X);
        col_reduce_kernel<<<N / 128, 1024>>>();
    }
    final_kernel<<<(size_t)N * (N / 4) / 256, 256>>>(X, out);
}

// round 3
// speedup vs baseline: 1.2395x; 1.2395x over previous
#include <cuda_runtime.h>

#define N       8192
#define GRID_A  148            // 1 block per SM, one wave
#define BLK_A   1024
#define NITER   10
#define PGROUPS 4
#define P_PER_G (GRID_A / PGROUPS)   // 37
#define LOG2E   1.4426950408889634f

// c and r are stored in LOG2 units (c*log2e, r*log2e)
__device__ float g_cl[N];
__device__ float g_rl[N];
__device__ float g_part[(size_t)GRID_A * N];

// ---------------------------------------------------------------------------
// zero the column log-offset vector (must happen every kernel_launch call)
// ---------------------------------------------------------------------------
__global__ void init_c_kernel() {
    int i = blockIdx.x * blockDim.x + threadIdx.x;
    if (i < N) g_cl[i] = 0.0f;
}

// ---------------------------------------------------------------------------
// One Sinkhorn iteration's matrix pass (software-pipelined, log2 domain):
//   e_ij  = exp2(x_ij*L - cl_j)
//   S_i   = sum_j e_ij          -> rl[i] = log2(S_i)
//   part[b,j] = sum_{i in block} e_ij / S_i
// 1024 threads, each owns 8 columns as 2 float4s: f4 index = tid + 1024*k.
// Next row's loads are issued BEFORE the current row's reduction so DRAM
// stays busy across the barrier. Single barrier per row via double-buffered
// per-warp partials + redundant second-level shuffle reduce.
// ---------------------------------------------------------------------------
__global__ void __launch_bounds__(BLK_A, 1)
row_pass_kernel(const float* __restrict__ X) {
    __shared__ float s_warp[2][32];

    const int tid  = threadIdx.x;
    const int lane = tid & 31;
    const int wid  = tid >> 5;
    const int b    = blockIdx.x;
    const int row0 = (int)(((long long)N * b)       / GRID_A);
    const int row1 = (int)(((long long)N * (b + 1)) / GRID_A);

    // column log2-offsets for this thread's 8 columns (registers)
    const float4* c4 = (const float4*)g_cl;
    float4 cl[2];
#pragma unroll
    for (int k = 0; k < 2; k++) cl[k] = __ldg(c4 + tid + 1024 * k);

    float4 acc[2];
#pragma unroll
    for (int k = 0; k < 2; k++) acc[k] = make_float4(0.f, 0.f, 0.f, 0.f);

    // preload first row
    float4 xc[2];
    {
        const float4* xr = (const float4*)(X + (size_t)row0 * N);
#pragma unroll
        for (int k = 0; k < 2; k++) xc[k] = __ldg(xr + tid + 1024 * k);
    }

    int buf = 0;
    for (int row = row0; row < row1; ++row, buf ^= 1) {
        // ---- prefetch next row (in flight across exp + reduce + barrier) ----
        float4 xn[2];
        if (row + 1 < row1) {
            const float4* xr = (const float4*)(X + (size_t)(row + 1) * N);
#pragma unroll
            for (int k = 0; k < 2; k++) xn[k] = __ldg(xr + tid + 1024 * k);
        }

        // ---- e = exp2(x*L - cl), row partial sum ----
        float4 e[2];
        float  psum = 0.0f;
#pragma unroll
        for (int k = 0; k < 2; k++) {
            e[k].x = exp2f(fmaf(xc[k].x, LOG2E, -cl[k].x));
            e[k].y = exp2f(fmaf(xc[k].y, LOG2E, -cl[k].y));
            e[k].z = exp2f(fmaf(xc[k].z, LOG2E, -cl[k].z));
            e[k].w = exp2f(fmaf(xc[k].w, LOG2E, -cl[k].w));
            psum += (e[k].x + e[k].y) + (e[k].z + e[k].w);
        }

        // ---- warp reduce ----
#pragma unroll
        for (int off = 16; off > 0; off >>= 1)
            psum += __shfl_xor_sync(0xffffffffu, psum, off);
        if (lane == 0) s_warp[buf][wid] = psum;
        __syncthreads();

        // ---- second level: every warp reduces all 32 partials (no 2nd bar) ----
        float v = s_warp[buf][lane];
#pragma unroll
        for (int off = 16; off > 0; off >>= 1)
            v += __shfl_xor_sync(0xffffffffu, v, off);

        const float rcp = __fdividef(1.0f, v);   // exp(-r_i) exactly
        if (tid == 0) g_rl[row] = __log2f(v);    // row log2-offset

#pragma unroll
        for (int k = 0; k < 2; k++) {
            acc[k].x = fmaf(e[k].x, rcp, acc[k].x);
            acc[k].y = fmaf(e[k].y, rcp, acc[k].y);
            acc[k].z = fmaf(e[k].z, rcp, acc[k].z);
            acc[k].w = fmaf(e[k].w, rcp, acc[k].w);
        }

        xc[0] = xn[0];
        xc[1] = xn[1];
    }

    float4* pp = (float4*)(g_part + (size_t)b * N);
#pragma unroll
    for (int k = 0; k < 2; k++) pp[tid + 1024 * k] = acc[k];
}

// ---------------------------------------------------------------------------
// Column reduce: cl[j] += log2( sum_b part[b][j] ).
// 64 blocks x 512 threads = (128 cols, 4 p-groups of 37 rows). Deterministic.
// ---------------------------------------------------------------------------
__global__ void __launch_bounds__(512)
col_reduce_kernel() {
    __shared__ float s[PGROUPS][128];
    const int jl = threadIdx.x & 127;
    const int pg = threadIdx.x >> 7;
    const int j  = blockIdx.x * 128 + jl;

    const float* base = g_part + (size_t)(pg * P_PER_G) * N + j;
    float a0 = 0.f, a1 = 0.f, a2 = 0.f, a3 = 0.f;
#pragma unroll
    for (int u = 0; u < 36; u += 4) {
        a0 += base[(size_t)(u + 0) * N];
        a1 += base[(size_t)(u + 1) * N];
        a2 += base[(size_t)(u + 2) * N];
        a3 += base[(size_t)(u + 3) * N];
    }
    a0 += base[(size_t)36 * N];                  // 37th row of the group
    s[pg][jl] = (a0 + a1) + (a2 + a3);
    __syncthreads();

    if (pg == 0) {
        float t = 0.0f;
#pragma unroll
        for (int q = 0; q < PGROUPS; q++) t += s[q][jl];
        g_cl[j] += __log2f(t);
    }
}

// ---------------------------------------------------------------------------
// Final: out[i,j] = exp2(x[i,j]*L - rl[i] - cl[j])
// ---------------------------------------------------------------------------
__global__ void __launch_bounds__(256)
final_kernel(const float* __restrict__ X, float* __restrict__ out) {
    const size_t idx = (size_t)blockIdx.x * blockDim.x + threadIdx.x; // float4 index
    const int    row = (int)(idx >> 11);        // N/4 = 2048 float4 per row
    const int    c4i = (int)(idx & 2047);

    const float  nrl = -__ldg(g_rl + row);
    const float4 cc  = __ldg(((const float4*)g_cl) + c4i);
    const float4 x   = __ldg(((const float4*)X) + idx);

    float4 o;
    o.x = exp2f(fmaf(x.x, LOG2E, nrl - cc.x));
    o.y = exp2f(fmaf(x.y, LOG2E, nrl - cc.y));
    o.z = exp2f(fmaf(x.z, LOG2E, nrl - cc.z));
    o.w = exp2f(fmaf(x.w, LOG2E, nrl - cc.w));
    ((float4*)out)[idx] = o;
}

// ---------------------------------------------------------------------------
extern "C" void kernel_launch(void* const* d_in, const int* in_sizes, int n_in,
                              void* d_out, int out_size) {
    const float* X   = (const float*)d_in[0];
    float*       out = (float*)d_out;
    (void)in_sizes; (void)n_in; (void)out_size;

    init_c_kernel<<<N / 256, 256>>>();
    for (int it = 0; it < NITER; ++it) {
        row_pass_kernel<<<GRID_A, BLK_A>>>(X);
        col_reduce_kernel<<<N / 128, 512>>>();
    }
    final_kernel<<<(size_t)N * (N / 4) / 256, 256>>>(X, out);
}